// round 14
// baseline (speedup 1.0000x reference)
#include <cuda_runtime.h>

#define BB 2
#define NN 262144
#define SS 24
#define TOT (BB*NN)
#define EPSV 1e-4f
#define NPART 64

// ---- scratch (no allocation allowed; __device__ globals) ----
__device__ float  g_wm[TOT];
__device__ float  g_u[TOT];
__device__ float  g_v[TOT];
__device__ double g_partA[NPART];   // |A| partials
__device__ double g_partV[NPART];   // valid partials
__device__ double g_partD[NPART];   // diff^2 partials
__device__ float  g_sinv;           // 1/(norm+1e-8), set by gather_v last block
__device__ unsigned g_count;        // completion counter (self-resetting)

// ---------------------------------------------------------------------------
__device__ __forceinline__ float warpReduceSum(float v) {
    #pragma unroll
    for (int o = 16; o > 0; o >>= 1) v += __shfl_down_sync(0xffffffffu, v, o);
    return v;
}

__device__ __forceinline__ void load_nbr24(const int* __restrict__ nbr,
                                           long long i, int* nn) {
    const int4* nb4 = (const int4*)(nbr + i * SS);
    #pragma unroll
    for (int k = 0; k < 6; k++) {
        int4 q = nb4[k];
        nn[4*k+0] = q.x; nn[4*k+1] = q.y; nn[4*k+2] = q.z; nn[4*k+3] = q.w;
    }
}

// Warp-private stage of 32 nodes x 25 G-coeffs (800 floats, linear copy).
__device__ __forceinline__ void warp_stage_g25(const float* __restrict__ G,
                                               int warpNode0, float* shw, int lane) {
    const float* gBase = G + (long long)warpNode0 * 25;
    #pragma unroll
    for (int k = 0; k < 25; k++)
        shw[k * 32 + lane] = gBase[k * 32 + lane];
    __syncwarp();
}

// Warp-private stage of 32 nodes x 24 Ao-coeffs, padded row 24->25.
__device__ __forceinline__ void warp_stage_a24(const float* __restrict__ Ao,
                                               int warpNode0, float* shw, int lane) {
    const float* aBase = Ao + (long long)warpNode0 * SS;
    #pragma unroll
    for (int k = 0; k < 24; k++) {
        int e = k * 32 + lane;          // e = m*24 + c
        shw[e + e / 24] = aBase[e];     // -> m*25 + c
    }
    __syncwarp();
}

// ---------------------------------------------------------------------------
// zero g_u and partial arrays (keeps g_u L2-resident for scatter)
__global__ __launch_bounds__(256) void k_zero() {
    long long i = (long long)blockIdx.x * blockDim.x + threadIdx.x;
    if (i < NPART) { g_partA[i] = 0.0; g_partV[i] = 0.0; g_partD[i] = 0.0; }
    float4* u4 = (float4*)g_u;
    if (i < TOT / 4) u4[i] = make_float4(0.f, 0.f, 0.f, 0.f);
}

// K1: wm = w*vm ; u += diag + G^T scatter (25 atomics/node). Unchanged (proven).
__global__ __launch_bounds__(256) void k_scatter(const float* __restrict__ G,
                                                 const float* __restrict__ w,
                                                 const float* __restrict__ vm,
                                                 const int* __restrict__ nbr) {
    __shared__ float sh[8 * 800];
    int tid  = threadIdx.x;
    int lane = tid & 31;
    int wid  = tid >> 5;
    int node0 = blockIdx.x * 256;
    long long i = node0 + tid;
    int base = (i >= NN) ? NN : 0;
    float* shw = sh + wid * 800;

    warp_stage_g25(G, node0 + wid * 32, shw, lane);
    const float* my = shw + lane * 25;

    float wmv = w[i] * vm[i];
    g_wm[i] = wmv;

    int nn[24];
    load_nbr24(nbr, i, nn);

    atomicAdd(&g_u[i], wmv * my[0]);                  // diagonal (coalesced)
    #pragma unroll
    for (int j = 0; j < SS; j++) {
        int nb = nn[j];
        if ((unsigned)nb < (unsigned)NN)
            atomicAdd(&g_u[base + nb], wmv * my[1 + j]);
    }
}

// K2: v = G u + eps*wm. Batched (8-wide) gathers, 32-reg cap for full occupancy.
// Also |A|/valid partials; last block computes g_sinv.
__global__ __launch_bounds__(256, 8) void k_gather_v(const float* __restrict__ G,
                                                     const float* __restrict__ Ad,
                                                     const float* __restrict__ Ao,
                                                     const float* __restrict__ vm,
                                                     const int* __restrict__ nbr) {
    __shared__ float sh[8 * 800];
    int tid  = threadIdx.x;
    int lane = tid & 31;
    int wid  = tid >> 5;
    int node0 = blockIdx.x * 256;
    long long i = node0 + tid;
    int base = (i >= NN) ? NN : 0;
    float* shw = sh + wid * 800;

    warp_stage_g25(G, node0 + wid * 32, shw, lane);
    const float* my = shw + lane * 25;

    const int4* nb4 = (const int4*)(nbr + i * SS);
    float acc = g_u[i] * my[0];
    #pragma unroll
    for (int b = 0; b < 3; b++) {
        int4 q0 = nb4[2*b], q1 = nb4[2*b+1];
        int nn[8] = {q0.x, q0.y, q0.z, q0.w, q1.x, q1.y, q1.z, q1.w};
        float xs[8];
        #pragma unroll
        for (int j = 0; j < 8; j++)
            xs[j] = ((unsigned)nn[j] < (unsigned)NN) ? g_u[base + nn[j]] : 0.f;
        #pragma unroll
        for (int j = 0; j < 8; j++)
            acc = fmaf(xs[j], my[1 + 8*b + j], acc);
    }
    g_v[i] = acc + EPSV * g_wm[i];

    // flat |A| partial (association-free bijection over Ao, coalesced float4)
    float v = vm[i];
    float s = fabsf(Ad[i]);
    const float4* A4 = (const float4*)Ao;             // TOT*6 float4 total
    #pragma unroll
    for (int k = 0; k < 6; k++) {
        float4 a = A4[(long long)k * TOT + i];
        s += fabsf(a.x) + fabsf(a.y) + fabsf(a.z) + fabsf(a.w);
    }
    float ws = warpReduceSum(s);
    float wv = warpReduceSum(v);
    if (lane == 0) {
        int slot = (blockIdx.x * 8 + wid) & (NPART - 1);
        atomicAdd(&g_partA[slot], (double)ws);
        atomicAdd(&g_partV[slot], (double)wv);
    }

    // last-block finalize: one warp reduces the 64 partials -> g_sinv
    __syncwarp();
    if (wid == 0) {
        unsigned ticket = 0;
        if (lane == 0) {
            __threadfence();
            ticket = atomicAdd(&g_count, 1u);
        }
        ticket = __shfl_sync(0xffffffffu, ticket, 0);
        if (ticket == gridDim.x - 1) {
            double a  = *((volatile double*)&g_partA[lane])
                      + *((volatile double*)&g_partA[lane + 32]);
            double vv = *((volatile double*)&g_partV[lane])
                      + *((volatile double*)&g_partV[lane + 32]);
            #pragma unroll
            for (int o = 16; o > 0; o >>= 1) {
                a  += __shfl_down_sync(0xffffffffu, a,  o);
                vv += __shfl_down_sync(0xffffffffu, vv, o);
            }
            if (lane == 0) {
                double norm = a / (vv * 25.0 + 1e-6);
                g_sinv = (float)(1.0 / (norm + 1e-8));
                g_count = 0u;           // reset for next replay
                __threadfence();
            }
        }
    }
}

// K3: y = A v ; z = y*g_sinv ; diff^2 warp-partials. Batched gathers, 32-reg cap.
__global__ __launch_bounds__(256, 8) void k_gather_y(const float* __restrict__ Ad,
                                                     const float* __restrict__ Ao,
                                                     const float* __restrict__ vm,
                                                     const int* __restrict__ nbr) {
    __shared__ float sh[8 * 800];
    int tid  = threadIdx.x;
    int lane = tid & 31;
    int wid  = tid >> 5;
    int node0 = blockIdx.x * 256;
    long long i = node0 + tid;
    int base = (i >= NN) ? NN : 0;
    float* shw = sh + wid * 800;

    warp_stage_a24(Ao, node0 + wid * 32, shw, lane);
    const float* my = shw + lane * 25;

    float s_inv = g_sinv;               // uniform scalar load

    const int4* nb4 = (const int4*)(nbr + i * SS);
    float acc = g_v[i] * Ad[i];
    #pragma unroll
    for (int b = 0; b < 3; b++) {
        int4 q0 = nb4[2*b], q1 = nb4[2*b+1];
        int nn[8] = {q0.x, q0.y, q0.z, q0.w, q1.x, q1.y, q1.z, q1.w};
        float xs[8];
        #pragma unroll
        for (int j = 0; j < 8; j++)
            xs[j] = ((unsigned)nn[j] < (unsigned)NN) ? g_v[base + nn[j]] : 0.f;
        #pragma unroll
        for (int j = 0; j < 8; j++)
            acc = fmaf(xs[j], my[8*b + j], acc);
    }

    float z = acc * s_inv;
    float d = (z - g_wm[i]) * vm[i];
    float wd = warpReduceSum(d * d);
    if (lane == 0) {
        int slot = (blockIdx.x * 8 + wid) & (NPART - 1);
        atomicAdd(&g_partD[slot], (double)wd);
    }
}

__global__ void k_final(float* out) {
    int t = threadIdx.x;                // 64 threads
    double d = g_partD[t];
    double v = g_partV[t];
    #pragma unroll
    for (int o = 16; o > 0; o >>= 1) {
        d += __shfl_down_sync(0xffffffffu, d, o);
        v += __shfl_down_sync(0xffffffffu, v, o);
    }
    __shared__ double shD[2], shV[2];
    if ((t & 31) == 0) { shD[t >> 5] = d; shV[t >> 5] = v; }
    __syncthreads();
    if (t == 0)
        out[0] = (float)((shD[0] + shD[1]) / (shV[0] + shV[1] + 1e-6));
}

// ---------------------------------------------------------------------------
extern "C" void kernel_launch(void* const* d_in, const int* in_sizes, int n_in,
                              void* d_out, int out_size) {
    const float* G   = (const float*)d_in[0];   // [2,N,25]
    const float* Ad  = (const float*)d_in[1];   // [2,N,1]
    const float* Ao  = (const float*)d_in[2];   // [2,N,24]
    const float* w   = (const float*)d_in[3];   // [2,N,1]
    const float* vm  = (const float*)d_in[4];   // [2,N,1]
    const int*   nbr = (const int*)d_in[5];     // [2,N,24] int32
    float* out = (float*)d_out;

    const int T = 256;
    const int nodeBlocks = TOT / T;             // 2048, exact
    const int zeroBlocks = TOT / 4 / T;         // 512

    k_zero    <<<zeroBlocks, T>>>();
    k_scatter <<<nodeBlocks, T>>>(G, w, vm, nbr);
    k_gather_v<<<nodeBlocks, T>>>(G, Ad, Ao, vm, nbr);
    k_gather_y<<<nodeBlocks, T>>>(Ad, Ao, vm, nbr);
    k_final   <<<1, 64>>>(out);
}

// round 15
// speedup vs baseline: 1.4854x; 1.4854x over previous
#include <cuda_runtime.h>
#include <cooperative_groups.h>
namespace cg = cooperative_groups;

#define NN 262144
#define SS 24
#define TOT (2*NN)
#define EPSV 1e-4f
#define NPART 64
#define NCHUNK 2048          // TOT / 256

// ---- scratch (no allocation allowed; __device__ globals) ----
__device__ float  g_wm[TOT];
__device__ float  g_u[TOT];
__device__ float  g_v[TOT];
__device__ double g_partA[NPART];
__device__ double g_partV[NPART];
__device__ double g_partD[NPART];

// ---------------------------------------------------------------------------
__device__ __forceinline__ float warpReduceSum(float v) {
    #pragma unroll
    for (int o = 16; o > 0; o >>= 1) v += __shfl_down_sync(0xffffffffu, v, o);
    return v;
}

__device__ __forceinline__ void load_nbr24(const int* __restrict__ nbr,
                                           long long i, int* nn) {
    const int4* nb4 = (const int4*)(nbr + i * SS);
    #pragma unroll
    for (int k = 0; k < 6; k++) {
        int4 q = nb4[k];
        nn[4*k+0] = q.x; nn[4*k+1] = q.y; nn[4*k+2] = q.z; nn[4*k+3] = q.w;
    }
}

__device__ __forceinline__ void warp_stage_g25(const float* __restrict__ G,
                                               int warpNode0, float* shw, int lane) {
    const float* gBase = G + (long long)warpNode0 * 25;
    #pragma unroll
    for (int k = 0; k < 25; k++)
        shw[k * 32 + lane] = gBase[k * 32 + lane];
    __syncwarp();
}

__device__ __forceinline__ void warp_stage_a24(const float* __restrict__ Ao,
                                               int warpNode0, float* shw, int lane) {
    const float* aBase = Ao + (long long)warpNode0 * SS;
    #pragma unroll
    for (int k = 0; k < 24; k++) {
        int e = k * 32 + lane;
        shw[e + e / 24] = aBase[e];
    }
    __syncwarp();
}

// ---------------------------------------------------------------------------
// Phase bodies (chunk c = 256 nodes), exactly the proven R11 interiors.
__device__ __forceinline__ void phase_scatter_chunk(int c, int tid, int lane, int wid,
        float* sh, const float* __restrict__ G, const float* __restrict__ w,
        const float* __restrict__ vm, const int* __restrict__ nbr) {
    int node0 = c * 256;
    long long i = node0 + tid;
    int base = (i >= NN) ? NN : 0;
    float* shw = sh + wid * 800;
    warp_stage_g25(G, node0 + wid * 32, shw, lane);
    const float* my = shw + lane * 25;

    float wmv = w[i] * vm[i];
    g_wm[i] = wmv;

    int nn[24];
    load_nbr24(nbr, i, nn);
    atomicAdd(&g_u[i], wmv * my[0]);
    #pragma unroll
    for (int j = 0; j < SS; j++) {
        int nb = nn[j];
        if ((unsigned)nb < (unsigned)NN)
            atomicAdd(&g_u[base + nb], wmv * my[1 + j]);
    }
    __syncwarp();
}

__device__ __forceinline__ void phase_gather_v_chunk(int c, int tid, int lane, int wid,
        float* sh, const float* __restrict__ G, const float* __restrict__ Ad,
        const float* __restrict__ Ao, const float* __restrict__ vm,
        const int* __restrict__ nbr) {
    int node0 = c * 256;
    long long i = node0 + tid;
    int base = (i >= NN) ? NN : 0;
    float* shw = sh + wid * 800;
    warp_stage_g25(G, node0 + wid * 32, shw, lane);
    const float* my = shw + lane * 25;

    int nn[24];
    load_nbr24(nbr, i, nn);
    float xs[24];
    #pragma unroll
    for (int j = 0; j < SS; j++)
        xs[j] = ((unsigned)nn[j] < (unsigned)NN) ? g_u[base + nn[j]] : 0.f;

    float acc = g_u[i] * my[0];
    #pragma unroll
    for (int j = 0; j < SS; j++)
        acc = fmaf(xs[j], my[1 + j], acc);
    g_v[i] = acc + EPSV * g_wm[i];

    float v = vm[i];
    float s = fabsf(Ad[i]);
    const float4* A4 = (const float4*)Ao;
    #pragma unroll
    for (int k = 0; k < 6; k++) {
        float4 a = A4[(long long)k * TOT + i];
        s += fabsf(a.x) + fabsf(a.y) + fabsf(a.z) + fabsf(a.w);
    }
    float ws = warpReduceSum(s);
    float wv = warpReduceSum(v);
    if (lane == 0) {
        int slot = (c * 8 + wid) & (NPART - 1);
        atomicAdd(&g_partA[slot], (double)ws);
        atomicAdd(&g_partV[slot], (double)wv);
    }
    __syncwarp();
}

__device__ __forceinline__ void phase_gather_y_chunk(int c, int tid, int lane, int wid,
        float* sh, float s_inv, const float* __restrict__ Ad,
        const float* __restrict__ Ao, const float* __restrict__ vm,
        const int* __restrict__ nbr) {
    int node0 = c * 256;
    long long i = node0 + tid;
    int base = (i >= NN) ? NN : 0;
    float* shw = sh + wid * 800;
    warp_stage_a24(Ao, node0 + wid * 32, shw, lane);
    const float* my = shw + lane * 25;

    int nn[24];
    load_nbr24(nbr, i, nn);
    float xs[24];
    #pragma unroll
    for (int j = 0; j < SS; j++)
        xs[j] = ((unsigned)nn[j] < (unsigned)NN) ? g_v[base + nn[j]] : 0.f;

    float acc = g_v[i] * Ad[i];
    #pragma unroll
    for (int j = 0; j < SS; j++)
        acc = fmaf(xs[j], my[j], acc);

    float z = acc * s_inv;
    float d = (z - g_wm[i]) * vm[i];
    float wd = warpReduceSum(d * d);
    if (lane == 0) {
        int slot = (c * 8 + wid) & (NPART - 1);
        atomicAdd(&g_partD[slot], (double)wd);
    }
    __syncwarp();
}

// Per-block s_inv: warp 0 reduces the 64 L2-resident partials, share via smem.
__device__ __forceinline__ float block_compute_sinv(int lane, int wid, float* s_sh) {
    if (wid == 0) {
        double a  = g_partA[lane] + g_partA[lane + 32];
        double vv = g_partV[lane] + g_partV[lane + 32];
        #pragma unroll
        for (int o = 16; o > 0; o >>= 1) {
            a  += __shfl_down_sync(0xffffffffu, a,  o);
            vv += __shfl_down_sync(0xffffffffu, vv, o);
        }
        if (lane == 0) {
            double norm = a / (vv * 25.0 + 1e-6);
            *s_sh = (float)(1.0 / (norm + 1e-8));
        }
    }
    __syncthreads();
    return *s_sh;
}

// ---------------------------------------------------------------------------
// Single cooperative kernel: all phases, grid.sync between them.
__global__ __launch_bounds__(256, 4) void k_fused(const float* __restrict__ G,
                                                  const float* __restrict__ Ad,
                                                  const float* __restrict__ Ao,
                                                  const float* __restrict__ w,
                                                  const float* __restrict__ vm,
                                                  const int* __restrict__ nbr,
                                                  float* __restrict__ out) {
    cg::grid_group grid = cg::this_grid();
    __shared__ float sh[8 * 800];
    __shared__ float s_sh;
    int tid  = threadIdx.x;
    int lane = tid & 31;
    int wid  = tid >> 5;

    // phase 0: zero g_u + partials
    for (long long idx = (long long)blockIdx.x * 256 + tid; idx < TOT / 4;
         idx += (long long)gridDim.x * 256)
        ((float4*)g_u)[idx] = make_float4(0.f, 0.f, 0.f, 0.f);
    if (blockIdx.x == 0 && tid < NPART) {
        g_partA[tid] = 0.0; g_partV[tid] = 0.0; g_partD[tid] = 0.0;
    }
    grid.sync();

    // phase 1: scatter
    for (int c = blockIdx.x; c < NCHUNK; c += gridDim.x)
        phase_scatter_chunk(c, tid, lane, wid, sh, G, w, vm, nbr);
    grid.sync();

    // phase 2: gather_v (+ |A|/valid partials)
    for (int c = blockIdx.x; c < NCHUNK; c += gridDim.x)
        phase_gather_v_chunk(c, tid, lane, wid, sh, G, Ad, Ao, vm, nbr);
    grid.sync();

    // phase 3: gather_y
    float s_inv = block_compute_sinv(lane, wid, &s_sh);
    for (int c = blockIdx.x; c < NCHUNK; c += gridDim.x)
        phase_gather_y_chunk(c, tid, lane, wid, sh, s_inv, Ad, Ao, vm, nbr);
    grid.sync();

    // final
    if (blockIdx.x == 0 && wid == 0) {
        double d = g_partD[lane] + g_partD[lane + 32];
        double v = g_partV[lane] + g_partV[lane + 32];
        #pragma unroll
        for (int o = 16; o > 0; o >>= 1) {
            d += __shfl_down_sync(0xffffffffu, d, o);
            v += __shfl_down_sync(0xffffffffu, v, o);
        }
        if (lane == 0)
            out[0] = (float)(d / (v + 1e-6));
    }
}

// ---------------------------------------------------------------------------
// Fallback path (R11 structure) if cooperative launch is unavailable.
__global__ __launch_bounds__(256) void k_zero() {
    long long i = (long long)blockIdx.x * blockDim.x + threadIdx.x;
    if (i < NPART) { g_partA[i] = 0.0; g_partV[i] = 0.0; g_partD[i] = 0.0; }
    float4* u4 = (float4*)g_u;
    if (i < TOT / 4) u4[i] = make_float4(0.f, 0.f, 0.f, 0.f);
}
__global__ __launch_bounds__(256) void k_scatter(const float* __restrict__ G,
                                                 const float* __restrict__ w,
                                                 const float* __restrict__ vm,
                                                 const int* __restrict__ nbr) {
    __shared__ float sh[8 * 800];
    phase_scatter_chunk(blockIdx.x, threadIdx.x, threadIdx.x & 31, threadIdx.x >> 5,
                        sh, G, w, vm, nbr);
}
__global__ __launch_bounds__(256) void k_gather_v(const float* __restrict__ G,
                                                  const float* __restrict__ Ad,
                                                  const float* __restrict__ Ao,
                                                  const float* __restrict__ vm,
                                                  const int* __restrict__ nbr) {
    __shared__ float sh[8 * 800];
    phase_gather_v_chunk(blockIdx.x, threadIdx.x, threadIdx.x & 31, threadIdx.x >> 5,
                         sh, G, Ad, Ao, vm, nbr);
}
__global__ __launch_bounds__(256) void k_gather_y(const float* __restrict__ Ad,
                                                  const float* __restrict__ Ao,
                                                  const float* __restrict__ vm,
                                                  const int* __restrict__ nbr) {
    __shared__ float sh[8 * 800];
    __shared__ float s_sh;
    int lane = threadIdx.x & 31, wid = threadIdx.x >> 5;
    float s_inv = block_compute_sinv(lane, wid, &s_sh);
    phase_gather_y_chunk(blockIdx.x, threadIdx.x, lane, wid, sh, s_inv, Ad, Ao, vm, nbr);
}
__global__ void k_final(float* out) {
    int t = threadIdx.x;                // 64 threads
    double d = g_partD[t];
    double v = g_partV[t];
    #pragma unroll
    for (int o = 16; o > 0; o >>= 1) {
        d += __shfl_down_sync(0xffffffffu, d, o);
        v += __shfl_down_sync(0xffffffffu, v, o);
    }
    __shared__ double shD[2], shV[2];
    if ((t & 31) == 0) { shD[t >> 5] = d; shV[t >> 5] = v; }
    __syncthreads();
    if (t == 0)
        out[0] = (float)((shD[0] + shD[1]) / (shV[0] + shV[1] + 1e-6));
}

// ---------------------------------------------------------------------------
extern "C" void kernel_launch(void* const* d_in, const int* in_sizes, int n_in,
                              void* d_out, int out_size) {
    const float* G   = (const float*)d_in[0];
    const float* Ad  = (const float*)d_in[1];
    const float* Ao  = (const float*)d_in[2];
    const float* w   = (const float*)d_in[3];
    const float* vm  = (const float*)d_in[4];
    const int*   nbr = (const int*)d_in[5];
    float* out = (float*)d_out;

    int dev = 0;
    cudaGetDevice(&dev);
    int sm = 0, perSM = 0;
    cudaDeviceGetAttribute(&sm, cudaDevAttrMultiProcessorCount, dev);
    cudaOccupancyMaxActiveBlocksPerMultiprocessor(&perSM, k_fused, 256, 0);
    int grid = sm * perSM;
    if (grid < 1) grid = 1;
    if (grid > NCHUNK) grid = NCHUNK;

    void* args[] = {(void*)&G, (void*)&Ad, (void*)&Ao, (void*)&w,
                    (void*)&vm, (void*)&nbr, (void*)&out};
    cudaError_t rc = cudaLaunchCooperativeKernel((const void*)k_fused,
                                                 dim3(grid), dim3(256),
                                                 args, 0, (cudaStream_t)0);
    if (rc != cudaSuccess) {
        cudaGetLastError();             // clear sticky error, use fallback path
        k_zero    <<<TOT / 4 / 256, 256>>>();
        k_scatter <<<NCHUNK, 256>>>(G, w, vm, nbr);
        k_gather_v<<<NCHUNK, 256>>>(G, Ad, Ao, vm, nbr);
        k_gather_y<<<NCHUNK, 256>>>(Ad, Ao, vm, nbr);
        k_final   <<<1, 64>>>(out);
    }
}

// round 16
// speedup vs baseline: 1.5935x; 1.0728x over previous
#include <cuda_runtime.h>

#define NN 262144
#define SS 24
#define TOT (2*NN)
#define EPSV 1e-4f
#define NPART 64
#define NCHUNK 2048          // TOT / 256
#define PGRID 912            // persistent grid: ~6 blocks/SM x 152 SMs

// ---- scratch (no allocation allowed; __device__ globals) ----
__device__ float  g_wm[TOT];
__device__ float  g_u[TOT];
__device__ float  g_v[TOT];
__device__ double g_partA[NPART];
__device__ double g_partV[NPART];
__device__ double g_partD[NPART];
__device__ float  g_sinv;
__device__ unsigned g_count;

// ---------------------------------------------------------------------------
__device__ __forceinline__ float warpReduceSum(float v) {
    #pragma unroll
    for (int o = 16; o > 0; o >>= 1) v += __shfl_down_sync(0xffffffffu, v, o);
    return v;
}

__device__ __forceinline__ void load_nbr24(const int* __restrict__ nbr,
                                           long long i, int* nn) {
    const int4* nb4 = (const int4*)(nbr + i * SS);
    #pragma unroll
    for (int k = 0; k < 6; k++) {
        int4 q = nb4[k];
        nn[4*k+0] = q.x; nn[4*k+1] = q.y; nn[4*k+2] = q.z; nn[4*k+3] = q.w;
    }
}

__device__ __forceinline__ void warp_stage_g25(const float* __restrict__ G,
                                               int warpNode0, float* shw, int lane) {
    const float* gBase = G + (long long)warpNode0 * 25;
    #pragma unroll
    for (int k = 0; k < 25; k++)
        shw[k * 32 + lane] = gBase[k * 32 + lane];
    __syncwarp();
}

__device__ __forceinline__ void warp_stage_a24(const float* __restrict__ Ao,
                                               int warpNode0, float* shw, int lane) {
    const float* aBase = Ao + (long long)warpNode0 * SS;
    #pragma unroll
    for (int k = 0; k < 24; k++) {
        int e = k * 32 + lane;
        shw[e + e / 24] = aBase[e];
    }
    __syncwarp();
}

// ---------------------------------------------------------------------------
// zero g_u and partial arrays
__global__ __launch_bounds__(256) void k_zero() {
    long long i = (long long)blockIdx.x * blockDim.x + threadIdx.x;
    if (i < NPART) { g_partA[i] = 0.0; g_partV[i] = 0.0; g_partD[i] = 0.0; }
    float4* u4 = (float4*)g_u;
    if (i < TOT / 4) u4[i] = make_float4(0.f, 0.f, 0.f, 0.f);
}

// K1 (persistent): wm = w*vm ; u += diag + G^T scatter (25 atomics/node)
__global__ __launch_bounds__(256) void k_scatter(const float* __restrict__ G,
                                                 const float* __restrict__ w,
                                                 const float* __restrict__ vm,
                                                 const int* __restrict__ nbr) {
    __shared__ float sh[8 * 800];
    int tid  = threadIdx.x;
    int lane = tid & 31;
    int wid  = tid >> 5;
    float* shw = sh + wid * 800;

    for (int c = blockIdx.x; c < NCHUNK; c += gridDim.x) {
        int node0 = c * 256;
        long long i = node0 + tid;
        int base = (i >= NN) ? NN : 0;

        warp_stage_g25(G, node0 + wid * 32, shw, lane);
        const float* my = shw + lane * 25;

        float wmv = w[i] * vm[i];
        g_wm[i] = wmv;

        int nn[24];
        load_nbr24(nbr, i, nn);

        atomicAdd(&g_u[i], wmv * my[0]);
        #pragma unroll
        for (int j = 0; j < SS; j++) {
            int nb = nn[j];
            if ((unsigned)nb < (unsigned)NN)
                atomicAdd(&g_u[base + nb], wmv * my[1 + j]);
        }
        __syncwarp();
    }
}

// K2 (persistent): v = G u + eps*wm (+ |A|/valid partials; last block -> g_sinv)
__global__ __launch_bounds__(256) void k_gather_v(const float* __restrict__ G,
                                                  const float* __restrict__ Ad,
                                                  const float* __restrict__ Ao,
                                                  const float* __restrict__ vm,
                                                  const int* __restrict__ nbr) {
    __shared__ float sh[8 * 800];
    int tid  = threadIdx.x;
    int lane = tid & 31;
    int wid  = tid >> 5;
    float* shw = sh + wid * 800;

    float accA = 0.f, accV = 0.f;

    for (int c = blockIdx.x; c < NCHUNK; c += gridDim.x) {
        int node0 = c * 256;
        long long i = node0 + tid;
        int base = (i >= NN) ? NN : 0;

        warp_stage_g25(G, node0 + wid * 32, shw, lane);
        const float* my = shw + lane * 25;

        int nn[24];
        load_nbr24(nbr, i, nn);
        float xs[24];
        #pragma unroll
        for (int j = 0; j < SS; j++)
            xs[j] = ((unsigned)nn[j] < (unsigned)NN) ? g_u[base + nn[j]] : 0.f;

        float acc = g_u[i] * my[0];
        #pragma unroll
        for (int j = 0; j < SS; j++)
            acc = fmaf(xs[j], my[1 + j], acc);
        g_v[i] = acc + EPSV * g_wm[i];

        // |A| stream: read-once -> evict-first (__ldcs) to protect g_u/g_v in L2
        float s = fabsf(Ad[i]);
        const float4* A4 = (const float4*)Ao;
        #pragma unroll
        for (int k = 0; k < 6; k++) {
            float4 a = __ldcs(&A4[(long long)k * TOT + i]);
            s += fabsf(a.x) + fabsf(a.y) + fabsf(a.z) + fabsf(a.w);
        }
        accA += s;
        accV += vm[i];
        __syncwarp();
    }

    float ws = warpReduceSum(accA);
    float wv = warpReduceSum(accV);
    if (lane == 0) {
        int slot = (blockIdx.x * 8 + wid) & (NPART - 1);
        atomicAdd(&g_partA[slot], (double)ws);
        atomicAdd(&g_partV[slot], (double)wv);
    }

    // last-block finalize: one warp reduces the 64 partials -> g_sinv
    __syncwarp();
    if (wid == 0) {
        unsigned ticket = 0;
        if (lane == 0) {
            __threadfence();
            ticket = atomicAdd(&g_count, 1u);
        }
        ticket = __shfl_sync(0xffffffffu, ticket, 0);
        if (ticket == gridDim.x - 1) {
            double a  = *((volatile double*)&g_partA[lane])
                      + *((volatile double*)&g_partA[lane + 32]);
            double vv = *((volatile double*)&g_partV[lane])
                      + *((volatile double*)&g_partV[lane + 32]);
            #pragma unroll
            for (int o = 16; o > 0; o >>= 1) {
                a  += __shfl_down_sync(0xffffffffu, a,  o);
                vv += __shfl_down_sync(0xffffffffu, vv, o);
            }
            if (lane == 0) {
                double norm = a / (vv * 25.0 + 1e-6);
                g_sinv = (float)(1.0 / (norm + 1e-8));
                g_count = 0u;
                __threadfence();
            }
        }
    }
}

// K3 (persistent): y = A v ; z = y*g_sinv ; diff^2 partials
__global__ __launch_bounds__(256) void k_gather_y(const float* __restrict__ Ad,
                                                  const float* __restrict__ Ao,
                                                  const float* __restrict__ vm,
                                                  const int* __restrict__ nbr) {
    __shared__ float sh[8 * 800];
    int tid  = threadIdx.x;
    int lane = tid & 31;
    int wid  = tid >> 5;
    float* shw = sh + wid * 800;

    float s_inv = g_sinv;               // uniform scalar load
    float accD = 0.f;

    for (int c = blockIdx.x; c < NCHUNK; c += gridDim.x) {
        int node0 = c * 256;
        long long i = node0 + tid;
        int base = (i >= NN) ? NN : 0;

        warp_stage_a24(Ao, node0 + wid * 32, shw, lane);
        const float* my = shw + lane * 25;

        int nn[24];
        load_nbr24(nbr, i, nn);
        float xs[24];
        #pragma unroll
        for (int j = 0; j < SS; j++)
            xs[j] = ((unsigned)nn[j] < (unsigned)NN) ? g_v[base + nn[j]] : 0.f;

        float acc = g_v[i] * Ad[i];
        #pragma unroll
        for (int j = 0; j < SS; j++)
            acc = fmaf(xs[j], my[j], acc);

        float z = acc * s_inv;
        float d = (z - g_wm[i]) * vm[i];
        accD += d * d;
        __syncwarp();
    }

    float wd = warpReduceSum(accD);
    if (lane == 0) {
        int slot = (blockIdx.x * 8 + wid) & (NPART - 1);
        atomicAdd(&g_partD[slot], (double)wd);
    }
}

__global__ void k_final(float* out) {
    int t = threadIdx.x;                // 64 threads
    double d = g_partD[t];
    double v = g_partV[t];
    #pragma unroll
    for (int o = 16; o > 0; o >>= 1) {
        d += __shfl_down_sync(0xffffffffu, d, o);
        v += __shfl_down_sync(0xffffffffu, v, o);
    }
    __shared__ double shD[2], shV[2];
    if ((t & 31) == 0) { shD[t >> 5] = d; shV[t >> 5] = v; }
    __syncthreads();
    if (t == 0)
        out[0] = (float)((shD[0] + shD[1]) / (shV[0] + shV[1] + 1e-6));
}

// ---------------------------------------------------------------------------
extern "C" void kernel_launch(void* const* d_in, const int* in_sizes, int n_in,
                              void* d_out, int out_size) {
    const float* G   = (const float*)d_in[0];   // [2,N,25]
    const float* Ad  = (const float*)d_in[1];   // [2,N,1]
    const float* Ao  = (const float*)d_in[2];   // [2,N,24]
    const float* w   = (const float*)d_in[3];   // [2,N,1]
    const float* vm  = (const float*)d_in[4];   // [2,N,1]
    const int*   nbr = (const int*)d_in[5];     // [2,N,24] int32
    float* out = (float*)d_out;

    const int T = 256;
    const int zeroBlocks = TOT / 4 / T;         // 512

    k_zero    <<<zeroBlocks, T>>>();
    k_scatter <<<PGRID, T>>>(G, w, vm, nbr);
    k_gather_v<<<PGRID, T>>>(G, Ad, Ao, vm, nbr);
    k_gather_y<<<PGRID, T>>>(Ad, Ao, vm, nbr);
    k_final   <<<1, 64>>>(out);
}

// round 17
// speedup vs baseline: 1.6134x; 1.0125x over previous
#include <cuda_runtime.h>

#define NN 262144
#define SS 24
#define TOT (2*NN)
#define EPSV 1e-4f
#define NPART 64
#define NCHUNK 2048          // TOT / 256
#define PGRID 912            // persistent grid: 6 blocks/SM x 152 SMs

// ---- scratch (no allocation allowed; __device__ globals) ----
__device__ float  g_wm[TOT];
__device__ float  g_u[TOT];
__device__ float  g_v[TOT];
__device__ double g_partA[NPART];
__device__ double g_partV[NPART];
__device__ double g_partD[NPART];
__device__ float  g_sinv;
__device__ unsigned g_count;

// ---------------------------------------------------------------------------
__device__ __forceinline__ float warpReduceSum(float v) {
    #pragma unroll
    for (int o = 16; o > 0; o >>= 1) v += __shfl_down_sync(0xffffffffu, v, o);
    return v;
}

__device__ __forceinline__ void load_nbr24(const int* __restrict__ nbr,
                                           long long i, int* nn) {
    const int4* nb4 = (const int4*)(nbr + i * SS);
    #pragma unroll
    for (int k = 0; k < 6; k++) {
        int4 q = nb4[k];
        nn[4*k+0] = q.x; nn[4*k+1] = q.y; nn[4*k+2] = q.z; nn[4*k+3] = q.w;
    }
}

__device__ __forceinline__ void warp_stage_g25(const float* __restrict__ G,
                                               int warpNode0, float* shw, int lane) {
    const float* gBase = G + (long long)warpNode0 * 25;
    #pragma unroll
    for (int k = 0; k < 25; k++)
        shw[k * 32 + lane] = gBase[k * 32 + lane];
    __syncwarp();
}

__device__ __forceinline__ void warp_stage_a24(const float* __restrict__ Ao,
                                               int warpNode0, float* shw, int lane) {
    const float* aBase = Ao + (long long)warpNode0 * SS;
    #pragma unroll
    for (int k = 0; k < 24; k++) {
        int e = k * 32 + lane;
        shw[e + e / 24] = aBase[e];
    }
    __syncwarp();
}

// ---------------------------------------------------------------------------
// zero g_u and partial arrays
__global__ __launch_bounds__(256) void k_zero() {
    long long i = (long long)blockIdx.x * blockDim.x + threadIdx.x;
    if (i < NPART) { g_partA[i] = 0.0; g_partV[i] = 0.0; g_partD[i] = 0.0; }
    float4* u4 = (float4*)g_u;
    if (i < TOT / 4) u4[i] = make_float4(0.f, 0.f, 0.f, 0.f);
}

// K1 (persistent, reg-capped): wm = w*vm ; u += diag + G^T scatter
__global__ __launch_bounds__(256, 6) void k_scatter(const float* __restrict__ G,
                                                    const float* __restrict__ w,
                                                    const float* __restrict__ vm,
                                                    const int* __restrict__ nbr) {
    __shared__ float sh[8 * 800];
    int tid  = threadIdx.x;
    int lane = tid & 31;
    int wid  = tid >> 5;
    float* shw = sh + wid * 800;

    for (int c = blockIdx.x; c < NCHUNK; c += PGRID) {
        int node0 = c * 256;
        long long i = node0 + tid;
        int base = (i >= NN) ? NN : 0;

        warp_stage_g25(G, node0 + wid * 32, shw, lane);
        const float* my = shw + lane * 25;

        float wmv = w[i] * vm[i];
        g_wm[i] = wmv;

        int nn[24];
        load_nbr24(nbr, i, nn);

        atomicAdd(&g_u[i], wmv * my[0]);
        #pragma unroll
        for (int j = 0; j < SS; j++) {
            int nb = nn[j];
            if ((unsigned)nb < (unsigned)NN)
                atomicAdd(&g_u[base + nb], wmv * my[1 + j]);
        }
        __syncwarp();
    }
}

// K2 (persistent, reg-capped): v = G u + eps*wm (+ partials; last block -> g_sinv)
__global__ __launch_bounds__(256, 6) void k_gather_v(const float* __restrict__ G,
                                                     const float* __restrict__ Ad,
                                                     const float* __restrict__ Ao,
                                                     const float* __restrict__ vm,
                                                     const int* __restrict__ nbr) {
    __shared__ float sh[8 * 800];
    int tid  = threadIdx.x;
    int lane = tid & 31;
    int wid  = tid >> 5;
    float* shw = sh + wid * 800;

    float accA = 0.f, accV = 0.f;

    for (int c = blockIdx.x; c < NCHUNK; c += PGRID) {
        int node0 = c * 256;
        long long i = node0 + tid;
        int base = (i >= NN) ? NN : 0;

        warp_stage_g25(G, node0 + wid * 32, shw, lane);
        const float* my = shw + lane * 25;

        int nn[24];
        load_nbr24(nbr, i, nn);
        float xs[24];
        #pragma unroll
        for (int j = 0; j < SS; j++)
            xs[j] = ((unsigned)nn[j] < (unsigned)NN) ? g_u[base + nn[j]] : 0.f;

        float acc = g_u[i] * my[0];
        #pragma unroll
        for (int j = 0; j < SS; j++)
            acc = fmaf(xs[j], my[1 + j], acc);
        g_v[i] = acc + EPSV * g_wm[i];

        // |A| stream: read-once -> evict-first, protects g_u/g_v in L2
        float s = fabsf(Ad[i]);
        const float4* A4 = (const float4*)Ao;
        #pragma unroll
        for (int k = 0; k < 6; k++) {
            float4 a = __ldcs(&A4[(long long)k * TOT + i]);
            s += fabsf(a.x) + fabsf(a.y) + fabsf(a.z) + fabsf(a.w);
        }
        accA += s;
        accV += vm[i];
        __syncwarp();
    }

    float ws = warpReduceSum(accA);
    float wv = warpReduceSum(accV);
    if (lane == 0) {
        int slot = (blockIdx.x * 8 + wid) & (NPART - 1);
        atomicAdd(&g_partA[slot], (double)ws);
        atomicAdd(&g_partV[slot], (double)wv);
    }

    // last-block finalize: one warp reduces the 64 partials -> g_sinv
    __syncwarp();
    if (wid == 0) {
        unsigned ticket = 0;
        if (lane == 0) {
            __threadfence();
            ticket = atomicAdd(&g_count, 1u);
        }
        ticket = __shfl_sync(0xffffffffu, ticket, 0);
        if (ticket == gridDim.x - 1) {
            double a  = *((volatile double*)&g_partA[lane])
                      + *((volatile double*)&g_partA[lane + 32]);
            double vv = *((volatile double*)&g_partV[lane])
                      + *((volatile double*)&g_partV[lane + 32]);
            #pragma unroll
            for (int o = 16; o > 0; o >>= 1) {
                a  += __shfl_down_sync(0xffffffffu, a,  o);
                vv += __shfl_down_sync(0xffffffffu, vv, o);
            }
            if (lane == 0) {
                double norm = a / (vv * 25.0 + 1e-6);
                g_sinv = (float)(1.0 / (norm + 1e-8));
                g_count = 0u;
                __threadfence();
            }
        }
    }
}

// K3 (persistent, reg-capped): y = A v ; z = y*g_sinv ; diff^2 partials
__global__ __launch_bounds__(256, 6) void k_gather_y(const float* __restrict__ Ad,
                                                     const float* __restrict__ Ao,
                                                     const float* __restrict__ vm,
                                                     const int* __restrict__ nbr) {
    __shared__ float sh[8 * 800];
    int tid  = threadIdx.x;
    int lane = tid & 31;
    int wid  = tid >> 5;
    float* shw = sh + wid * 800;

    float s_inv = g_sinv;               // uniform scalar load
    float accD = 0.f;

    for (int c = blockIdx.x; c < NCHUNK; c += PGRID) {
        int node0 = c * 256;
        long long i = node0 + tid;
        int base = (i >= NN) ? NN : 0;

        warp_stage_a24(Ao, node0 + wid * 32, shw, lane);
        const float* my = shw + lane * 25;

        int nn[24];
        load_nbr24(nbr, i, nn);
        float xs[24];
        #pragma unroll
        for (int j = 0; j < SS; j++)
            xs[j] = ((unsigned)nn[j] < (unsigned)NN) ? g_v[base + nn[j]] : 0.f;

        float acc = g_v[i] * Ad[i];
        #pragma unroll
        for (int j = 0; j < SS; j++)
            acc = fmaf(xs[j], my[j], acc);

        float z = acc * s_inv;
        float d = (z - g_wm[i]) * vm[i];
        accD += d * d;
        __syncwarp();
    }

    float wd = warpReduceSum(accD);
    if (lane == 0) {
        int slot = (blockIdx.x * 8 + wid) & (NPART - 1);
        atomicAdd(&g_partD[slot], (double)wd);
    }
}

__global__ void k_final(float* out) {
    int t = threadIdx.x;                // 64 threads
    double d = g_partD[t];
    double v = g_partV[t];
    #pragma unroll
    for (int o = 16; o > 0; o >>= 1) {
        d += __shfl_down_sync(0xffffffffu, d, o);
        v += __shfl_down_sync(0xffffffffu, v, o);
    }
    __shared__ double shD[2], shV[2];
    if ((t & 31) == 0) { shD[t >> 5] = d; shV[t >> 5] = v; }
    __syncthreads();
    if (t == 0)
        out[0] = (float)((shD[0] + shD[1]) / (shV[0] + shV[1] + 1e-6));
}

// ---------------------------------------------------------------------------
extern "C" void kernel_launch(void* const* d_in, const int* in_sizes, int n_in,
                              void* d_out, int out_size) {
    const float* G   = (const float*)d_in[0];   // [2,N,25]
    const float* Ad  = (const float*)d_in[1];   // [2,N,1]
    const float* Ao  = (const float*)d_in[2];   // [2,N,24]
    const float* w   = (const float*)d_in[3];   // [2,N,1]
    const float* vm  = (const float*)d_in[4];   // [2,N,1]
    const int*   nbr = (const int*)d_in[5];     // [2,N,24] int32
    float* out = (float*)d_out;

    const int T = 256;
    const int zeroBlocks = TOT / 4 / T;         // 512

    k_zero    <<<zeroBlocks, T>>>();
    k_scatter <<<PGRID, T>>>(G, w, vm, nbr);
    k_gather_v<<<PGRID, T>>>(G, Ad, Ao, vm, nbr);
    k_gather_y<<<PGRID, T>>>(Ad, Ao, vm, nbr);
    k_final   <<<1, 64>>>(out);
}